// round 4
// baseline (speedup 1.0000x reference)
#include <cuda_runtime.h>
#include <cstdint>

// ---------------- problem constants ----------------
#define C_CORES 64
#define D_EMB   128
#define CD      (C_CORES * D_EMB)        // 8192 floats = 32 KB per table

// ---------------- K1 geometry ----------------
#define TABLES  4                        // table groups per block
#define WPT     4                        // warps per table (column split)
#define K1_TPB  (TABLES * WPT * 32)      // 512 threads
#define BATCH   16                       // qubit rows per staged batch (8 KB)
#define MAX_BLK 160

// dynamic smem: 4 tables (128 KB) + 4 groups * 2 bufs * 8 KB staging (64 KB)
#define STAGE_BASE   (TABLES * CD)                       // float index
#define K1_SMEM_FLT  (TABLES * CD + TABLES * 2 * BATCH * D_EMB)

// ---------------- global scratch ----------------
__device__ float              g_partial[(size_t)MAX_BLK * CD];
__device__ unsigned long long g_maskarr[MAX_BLK];
__device__ float              g_E[CD];

__device__ __forceinline__ float neg_inf() { return __int_as_float(0xff800000); }

__device__ __forceinline__ uint32_t smem_u32(const void* p) {
    uint32_t a;
    asm("{ .reg .u64 t; cvta.to.shared.u64 t, %1; cvt.u32.u64 %0, t; }" : "=r"(a) : "l"(p));
    return a;
}

__device__ __forceinline__ void mbar_init(uint32_t addr, uint32_t cnt) {
    asm volatile("mbarrier.init.shared.b64 [%0], %1;" :: "r"(addr), "r"(cnt) : "memory");
}

__device__ __forceinline__ void mbar_wait(uint32_t addr, uint32_t parity) {
    asm volatile(
        "{\n\t.reg .pred P;\n"
        "W_%=:\n\t"
        "mbarrier.try_wait.parity.acquire.cta.shared::cta.b64 P, [%0], %1, 0x989680;\n\t"
        "@P bra D_%=;\n\t"
        "bra W_%=;\n"
        "D_%=:\n\t}"
        :: "r"(addr), "r"(parity) : "memory");
}

__device__ __forceinline__ void issue_bulk(uint32_t dst_smem, const float* src,
                                           uint32_t bytes, uint32_t mbar) {
    asm volatile("mbarrier.arrive.expect_tx.shared.b64 _, [%0], %1;"
                 :: "r"(mbar), "r"(bytes) : "memory");
    asm volatile("cp.async.bulk.shared::cta.global.mbarrier::complete_tx::bytes "
                 "[%0], [%1], %2, [%3];"
                 :: "r"(dst_smem), "l"(src), "r"(bytes), "r"(mbar) : "memory");
}

// =====================================================================
// K1: streaming segment-max with TMA-style bulk-copy double buffering.
// 4 table groups x 4 warps; each warp owns 32 columns of its table.
// The async engine streams qubit rows into smem while warps run the
// shared-memory RMW max chain on the previous batch.
// =====================================================================
__global__ __launch_bounds__(K1_TPB, 1)
void k1_segmax(const int* __restrict__ assign,
               const float* __restrict__ emb,
               int Q)
{
    extern __shared__ float sm[];
    __shared__ unsigned long long s_mbar[TABLES * 2];
    __shared__ unsigned char s_seen[C_CORES];

    const int tid    = threadIdx.x;
    const int wid    = tid >> 5;
    const int lane   = tid & 31;
    const int g      = wid >> 2;            // table group 0..3
    const int col    = (wid & 3) * 32 + lane;
    const int wg_tid = tid & 127;           // thread id within group
    float* tab = sm + g * CD;

    // init tables, seen flags, mbarriers
    {
        float4 ninf4 = make_float4(neg_inf(), neg_inf(), neg_inf(), neg_inf());
        float4* s4 = (float4*)sm;
        for (int i = tid; i < TABLES * CD / 4; i += K1_TPB) s4[i] = ninf4;
        if (tid < C_CORES) s_seen[tid] = 0;
        if (tid < TABLES * 2) mbar_init(smem_u32(&s_mbar[tid]), 1);
    }
    __syncthreads();

    // qubit chunk for this group
    const int ngroups = gridDim.x * TABLES;
    const int rgid    = blockIdx.x * TABLES + g;
    const int chunk   = (Q + ngroups - 1) / ngroups;
    const int q0      = rgid * chunk;
    const int q1      = (q0 + chunk < Q) ? (q0 + chunk) : Q;
    const int NB      = (q1 > q0) ? (q1 - q0 + BATCH - 1) / BATCH : 0;

    const uint32_t mb0 = smem_u32(&s_mbar[g * 2 + 0]);
    const uint32_t mb1 = smem_u32(&s_mbar[g * 2 + 1]);
    float* stage0 = sm + STAGE_BASE + (g * 2 + 0) * BATCH * D_EMB;
    float* stage1 = sm + STAGE_BASE + (g * 2 + 1) * BATCH * D_EMB;
    const uint32_t st0a = smem_u32(stage0);
    const uint32_t st1a = smem_u32(stage1);

    // prologue: fill both buffers
    if (wg_tid == 0) {
        if (NB > 0) {
            int rows = min(BATCH, q1 - q0);
            issue_bulk(st0a, emb + (size_t)q0 * D_EMB, rows * D_EMB * 4, mb0);
        }
        if (NB > 1) {
            int qb = q0 + BATCH;
            int rows = min(BATCH, q1 - qb);
            issue_bulk(st1a, emb + (size_t)qb * D_EMB, rows * D_EMB * 4, mb1);
        }
    }

    for (int b = 0; b < NB; b++) {
        const int buf = b & 1;
        mbar_wait(buf ? mb1 : mb0, (b >> 1) & 1);

        const int qb   = q0 + b * BATCH;
        const int rows = min(BATCH, q1 - qb);
        const float* st = (buf ? stage1 : stage0) + col;

#pragma unroll
        for (int r = 0; r < BATCH; r++) {
            if (r < rows) {
                int   c = __ldg(assign + qb + r);        // warp-uniform, L1-hit
                float v = st[r * D_EMB];                 // LDS from staged row
                float* p = tab + c * D_EMB + col;
                if (v > *p) *p = v;                      // private column -> race-free
                if (wg_tid == 0) s_seen[c] = 1;
            }
        }

        asm volatile("bar.sync %0, 128;" :: "r"(g + 1) : "memory");

        if (wg_tid == 0 && b + 2 < NB) {                 // refill just-consumed buffer
            int qn   = q0 + (b + 2) * BATCH;
            int rown = min(BATCH, q1 - qn);
            issue_bulk(buf ? st1a : st0a, emb + (size_t)qn * D_EMB,
                       rown * D_EMB * 4, buf ? mb1 : mb0);
        }
    }
    __syncthreads();

    // merge 4 tables -> per-block partial (plain stores, L2-resident)
    {
        const float4* s4 = (const float4*)sm;
        float4* g4 = (float4*)(g_partial + (size_t)blockIdx.x * CD);
        for (int i = tid; i < CD / 4; i += K1_TPB) {
            float4 m = s4[i];
#pragma unroll
            for (int r = 1; r < TABLES; r++) {
                float4 o = s4[r * (CD / 4) + i];
                m.x = fmaxf(m.x, o.x); m.y = fmaxf(m.y, o.y);
                m.z = fmaxf(m.z, o.z); m.w = fmaxf(m.w, o.w);
            }
            g4[i] = m;
        }
    }
    if (wid == 0) {
        unsigned b0 = __ballot_sync(0xffffffffu, s_seen[lane]      != 0);
        unsigned b1 = __ballot_sync(0xffffffffu, s_seen[lane + 32] != 0);
        if (lane == 0)
            g_maskarr[blockIdx.x] = ((unsigned long long)b1 << 32) | (unsigned long long)b0;
    }
}

// =====================================================================
// K2: reduce per-block partials -> E (with padding). One block per core.
// =====================================================================
__global__ __launch_bounds__(512)
void k2_reduce(const float* __restrict__ padding_emb, int nparts)
{
    __shared__ float sred[4][D_EMB];
    __shared__ unsigned long long s_m;

    const int c   = blockIdx.x;
    const int tid = threadIdx.x;
    const int t   = tid & 127;
    const int s   = tid >> 7;

    if (tid == 0) s_m = 0ull;
    __syncthreads();
    if (tid < nparts) atomicOr(&s_m, g_maskarr[tid]);

    float m = neg_inf();
    const float* pp = g_partial + (size_t)c * D_EMB + t;
#pragma unroll 8
    for (int p = s; p < nparts; p += 4)
        m = fmaxf(m, pp[(size_t)p * CD]);
    sred[s][t] = m;
    __syncthreads();

    if (s == 0) {
        float mm = fmaxf(fmaxf(sred[0][t], sred[1][t]), fmaxf(sred[2][t], sred[3][t]));
        float e = ((s_m >> c) & 1ull) ? mm : padding_emb[t];
        g_E[c * D_EMB + t] = e;
    }
}

// =====================================================================
// K3: out = relu(E@W_self + (con@E)@W_msg + b)   (associativity fuse)
// One block per core, 512 threads, everything 4-way split.
// =====================================================================
__global__ __launch_bounds__(512)
void k3_epilogue(const float* __restrict__ core_con,
                 const float* __restrict__ W_self,
                 const float* __restrict__ W_msg,
                 const float* __restrict__ bvec,
                 float* __restrict__ out)
{
    __shared__ float sE[C_CORES][D_EMB];   // 32 KB
    __shared__ float sMp[4][D_EMB];
    __shared__ float sM[D_EMB];
    __shared__ float sO[4][D_EMB];

    const int c   = blockIdx.x;
    const int tid = threadIdx.x;
    const int t   = tid & 127;
    const int s   = tid >> 7;

    // parallel fill of E (each slice loads 16 rows)
#pragma unroll
    for (int j = s * 16; j < s * 16 + 16; j++)
        sE[j][t] = __ldg(&g_E[j * D_EMB + t]);
    __syncthreads();

    // Msum[t] = sum_j con[c,j] * E[j,t]   (j split 4 ways)
    {
        float a = 0.f;
#pragma unroll
        for (int j = s * 16; j < s * 16 + 16; j++)
            a = fmaf(__ldg(&core_con[c * C_CORES + j]), sE[j][t], a);
        sMp[s][t] = a;
    }
    __syncthreads();
    if (s == 0)
        sM[t] = (sMp[0][t] + sMp[1][t]) + (sMp[2][t] + sMp[3][t]);
    __syncthreads();

    // GEMMs, k split 4 ways
    float a0 = 0.f, a1 = 0.f;
#pragma unroll
    for (int k = s * 32; k < s * 32 + 32; k++) {
        a0 = fmaf(sE[c][k], __ldg(&W_self[k * D_EMB + t]), a0);
        a1 = fmaf(sM[k],    __ldg(&W_msg [k * D_EMB + t]), a1);
    }
    sO[s][t] = a0 + a1;
    __syncthreads();
    if (s == 0) {
        float r = (sO[0][t] + sO[1][t]) + (sO[2][t] + sO[3][t]) + bvec[t];
        out[c * D_EMB + t] = fmaxf(r, 0.f);
    }
}

// ---------------- launch ----------------
extern "C" void kernel_launch(void* const* d_in, const int* in_sizes, int n_in,
                              void* d_out, int out_size)
{
    const int*   assign      = (const int*)  d_in[0];
    const float* emb         = (const float*)d_in[1];
    const float* padding_emb = (const float*)d_in[2];
    const float* core_con    = (const float*)d_in[3];
    const float* W_self      = (const float*)d_in[4];
    const float* W_msg       = (const float*)d_in[5];
    const float* bvec        = (const float*)d_in[6];
    float* out = (float*)d_out;

    const int Q = in_sizes[0];

    int nsm = 148;
    cudaDeviceGetAttribute(&nsm, cudaDevAttrMultiProcessorCount, 0);
    if (nsm > MAX_BLK) nsm = MAX_BLK;

    const int smem = K1_SMEM_FLT * (int)sizeof(float);   // 192 KB
    cudaFuncSetAttribute(k1_segmax, cudaFuncAttributeMaxDynamicSharedMemorySize, smem);

    k1_segmax<<<nsm, K1_TPB, smem>>>(assign, emb, Q);
    k2_reduce<<<C_CORES, 512>>>(padding_emb, nsm);
    k3_epilogue<<<C_CORES, 512>>>(core_con, W_self, W_msg, bvec, out);
}

// round 5
// speedup vs baseline: 1.3367x; 1.3367x over previous
#include <cuda_runtime.h>
#include <cstdint>

// ---------------- problem constants ----------------
#define C_CORES 64
#define D_EMB   128
#define CD      (C_CORES * D_EMB)     // 8192
#define TPB     512                   // 16 warps = 16 cores per block
#define GBUF    8                     // buffered matched rows per double-step

// ---------------- global scratch (zero-init; kernel restores zeros) ------
__device__ unsigned int g_tab[CD];    // encoded segment-max table
__device__ int g_a1, g_d1, g_a3, g_d3;// self-cleaning barrier counters

// order-preserving float <-> uint encoding (enc(x) != 0 for all finite x)
__device__ __forceinline__ unsigned int enc(float f) {
    unsigned int u = __float_as_uint(f);
    return (u & 0x80000000u) ? ~u : (u | 0x80000000u);
}
__device__ __forceinline__ float dec(unsigned int u) {
    u = (u & 0x80000000u) ? (u & 0x7fffffffu) : ~u;
    return __uint_as_float(u);
}
__device__ __forceinline__ float neg_inf() { return __int_as_float(0xff800000); }

// guarded int4 assign load (OOB -> -1, never matches a core)
__device__ __forceinline__ int4 ld_a4(const int* __restrict__ a, int i, int Q) {
    if (i + 3 < Q) return __ldg((const int4*)(a + i));
    int4 r;
    r.x = (i     < Q) ? __ldg(a + i)     : -1;
    r.y = (i + 1 < Q) ? __ldg(a + i + 1) : -1;
    r.z = (i + 2 < Q) ? __ldg(a + i + 2) : -1;
    r.w = (i + 3 < Q) ? __ldg(a + i + 3) : -1;
    return r;
}

#define FMAX4(d, v) { d.x = fmaxf(d.x, v.x); d.y = fmaxf(d.y, v.y); \
                      d.z = fmaxf(d.z, v.z); d.w = fmaxf(d.w, v.w); }

// process one ballot mask: gather qids into qb, overflow -> immediate fmax
#define PROC_MASK(MM, OFF, COMP) {                                          \
    unsigned _m = (MM);                                                     \
    while (_m) {                                                            \
        int _l = __ffs(_m) - 1; _m &= _m - 1;                               \
        int _q = base + (OFF) + 4 * _l + (COMP);                            \
        if (nq < GBUF) qb[nq++] = _q;                                       \
        else { float4 _v = __ldg(e4 + (size_t)_q * 32 + lane); FMAX4(rmx, _v); } \
    } }

__global__ __launch_bounds__(TPB, 1)
void fused_all(const int*   __restrict__ assign,
               const float* __restrict__ emb,
               const float* __restrict__ padding_emb,
               const float* __restrict__ core_con,
               const float* __restrict__ W_self,
               const float* __restrict__ W_msg,
               const float* __restrict__ bvec,
               float*       __restrict__ out,
               int Q, int chunk)
{
    const int tid  = threadIdx.x;
    const int wid  = tid >> 5;
    const int lane = tid & 31;
    const int grid = gridDim.x;

    // ================= phase 1: register segmax, warp = one core =========
    {
        const int core = (blockIdx.x & 3) * 16 + wid;   // coregroup 0..3
        const int q0   = (blockIdx.x >> 2) * chunk;     // split id
        const float4* e4 = (const float4*)emb;

        float4 rmx = make_float4(neg_inf(), neg_inf(), neg_inf(), neg_inf());
        bool seen = false;

        if (q0 < Q) {
            const int nds = (min(chunk, Q - q0) + 255) / 256;  // double-steps
            int4 a0 = ld_a4(assign, q0 +       4 * lane, Q);
            int4 a1 = ld_a4(assign, q0 + 128 + 4 * lane, Q);

            for (int s = 0; s < nds; s++) {
                const int base = q0 + s * 256;
                int4 n0, n1;
                if (s + 1 < nds) {
                    n0 = ld_a4(assign, base + 256 +       4 * lane, Q);
                    n1 = ld_a4(assign, base + 256 + 128 + 4 * lane, Q);
                } else {
                    n0 = make_int4(-1, -1, -1, -1);
                    n1 = n0;
                }

                unsigned m0 = __ballot_sync(0xffffffffu, a0.x == core);
                unsigned m1 = __ballot_sync(0xffffffffu, a0.y == core);
                unsigned m2 = __ballot_sync(0xffffffffu, a0.z == core);
                unsigned m3 = __ballot_sync(0xffffffffu, a0.w == core);
                unsigned m4 = __ballot_sync(0xffffffffu, a1.x == core);
                unsigned m5 = __ballot_sync(0xffffffffu, a1.y == core);
                unsigned m6 = __ballot_sync(0xffffffffu, a1.z == core);
                unsigned m7 = __ballot_sync(0xffffffffu, a1.w == core);

                int nq = 0; int qb[GBUF];
                PROC_MASK(m0,   0, 0); PROC_MASK(m1,   0, 1);
                PROC_MASK(m2,   0, 2); PROC_MASK(m3,   0, 3);
                PROC_MASK(m4, 128, 0); PROC_MASK(m5, 128, 1);
                PROC_MASK(m6, 128, 2); PROC_MASK(m7, 128, 3);

                seen |= (nq > 0);

                // issue ALL row loads before any consumption -> high MLP
                float4 v[GBUF];
#pragma unroll
                for (int i = 0; i < GBUF; i++)
                    if (i < nq) v[i] = __ldg(e4 + (size_t)qb[i] * 32 + lane);
#pragma unroll
                for (int i = 0; i < GBUF; i++)
                    if (i < nq) FMAX4(rmx, v[i]);

                a0 = n0; a1 = n1;
            }
        }

        if (seen) {   // warp-uniform; fold into global encoded table
            unsigned int* p = g_tab + core * D_EMB + lane * 4;
            atomicMax(p + 0, enc(rmx.x));
            atomicMax(p + 1, enc(rmx.y));
            atomicMax(p + 2, enc(rmx.z));
            atomicMax(p + 3, enc(rmx.w));
        }
    }

    // ================= grid barrier #1 (self-cleaning) ====================
    __threadfence();
    __syncthreads();
    if (blockIdx.x >= C_CORES) {          // non-epilogue blocks: arrive + exit
        if (tid == 0) atomicAdd(&g_a1, 1);
        return;
    }
    if (tid == 0) {
        atomicAdd(&g_a1, 1);
        while (atomicAdd(&g_a1, 0) < grid) __nanosleep(64);
        if (atomicAdd(&g_d1, 1) == C_CORES - 1) {   // last departer resets
            atomicExch(&g_a1, 0);
            atomicExch(&g_d1, 0);
        }
        __threadfence();
    }
    __syncthreads();

    // ================= phase 2: decode E, epilogue GNN ====================
    __shared__ float sE[C_CORES][D_EMB];   // 32 KB
    __shared__ float sMp[4][D_EMB];
    __shared__ float sM[D_EMB];
    __shared__ float sO[4][D_EMB];

    const int c = blockIdx.x;
    const int t = tid & 127;
    const int s = tid >> 7;

    {
        const float pad = __ldg(&padding_emb[t]);
#pragma unroll
        for (int j = s * 16; j < s * 16 + 16; j++) {
            unsigned int u = g_tab[j * D_EMB + t];
            sE[j][t] = u ? dec(u) : pad;      // u==0 <=> core never written
        }
    }
    __syncthreads();

    // -------- grid barrier #3 among the 64 epilogue blocks (all read done)
    if (tid == 0) {
        atomicAdd(&g_a3, 1);
        while (atomicAdd(&g_a3, 0) < C_CORES) __nanosleep(64);
        if (atomicAdd(&g_d3, 1) == C_CORES - 1) {
            atomicExch(&g_a3, 0);
            atomicExch(&g_d3, 0);
        }
        __threadfence();
    }
    __syncthreads();

    // clear this block's slice of g_tab (restore zero state for next replay)
    if (tid < 32) ((uint4*)g_tab)[c * 32 + tid] = make_uint4(0, 0, 0, 0);

    // Msum[t] = sum_j con[c,j] * E[j,t]   (j split 4 ways)
    {
        float a = 0.f;
#pragma unroll
        for (int j = s * 16; j < s * 16 + 16; j++)
            a = fmaf(__ldg(&core_con[c * C_CORES + j]), sE[j][t], a);
        sMp[s][t] = a;
    }
    __syncthreads();
    if (s == 0)
        sM[t] = (sMp[0][t] + sMp[1][t]) + (sMp[2][t] + sMp[3][t]);
    __syncthreads();

    // out = relu(E@W_self + Msum@W_msg + b), k split 4 ways
    float a0 = 0.f, a1 = 0.f;
#pragma unroll
    for (int k = s * 32; k < s * 32 + 32; k++) {
        a0 = fmaf(sE[c][k], __ldg(&W_self[k * D_EMB + t]), a0);
        a1 = fmaf(sM[k],    __ldg(&W_msg [k * D_EMB + t]), a1);
    }
    sO[s][t] = a0 + a1;
    __syncthreads();
    if (s == 0) {
        float r = (sO[0][t] + sO[1][t]) + (sO[2][t] + sO[3][t]) + __ldg(&bvec[t]);
        out[c * D_EMB + t] = fmaxf(r, 0.f);
    }
}

// ---------------- launch ----------------
extern "C" void kernel_launch(void* const* d_in, const int* in_sizes, int n_in,
                              void* d_out, int out_size)
{
    const int*   assign      = (const int*)  d_in[0];
    const float* emb         = (const float*)d_in[1];
    const float* padding_emb = (const float*)d_in[2];
    const float* core_con    = (const float*)d_in[3];
    const float* W_self      = (const float*)d_in[4];
    const float* W_msg       = (const float*)d_in[5];
    const float* bvec        = (const float*)d_in[6];
    float* out = (float*)d_out;

    const int Q = in_sizes[0];

    int nsm = 148;
    cudaDeviceGetAttribute(&nsm, cudaDevAttrMultiProcessorCount, 0);

    int grid = (nsm / 4) * 4;                    // 4 coregroups x nsplits
    if (grid < 64) grid = 64;                    // safety (never on GB300)
    const int nsplits = grid / 4;
    int chunk = (Q + nsplits - 1) / nsplits;     // per-split qubits
    chunk = (chunk + 255) & ~255;                // double-step granularity

    fused_all<<<grid, TPB>>>(assign, emb, padding_emb, core_con,
                             W_self, W_msg, bvec, out, Q, chunk);
}